// round 1
// baseline (speedup 1.0000x reference)
#include <cuda_runtime.h>
#include <math.h>

// FRAP q-value kernel, GB300 sm_103a.
// One warp per batch element. Algebraic factorization:
//   u[p] = lcA @ pairs[p] + lc_b ;  v[p] = lcB @ pairs[p]
//   x[i,j] = relu(u[i] + v[j]) ; comb = x * rsel[comp_mask]
//   y = relu(h_w @ comb + h_b) ; s = bm_w . y + bm_b ; q[i] = sum_j s[i,j]
// rsel (two 20-vectors) precomputed per block. Hidden GEMM uses packed
// fma.rn.f32x2 with broadcast LDS.64 of h_w rows.

typedef unsigned long long ull;

__device__ __forceinline__ ull ffma2(ull a, ull b, ull c) {
    ull d;
    asm("fma.rn.f32x2 %0, %1, %2, %3;" : "=l"(d) : "l"(a), "l"(b), "l"(c));
    return d;
}
__device__ __forceinline__ ull pk2(float lo, float hi) {
    ull r;
    asm("mov.b64 %0, {%1, %2};" : "=l"(r) : "f"(lo), "f"(hi));
    return r;
}
__device__ __forceinline__ void upk2(ull v, float& lo, float& hi) {
    asm("mov.b64 {%0, %1}, %2;" : "=f"(lo), "=f"(hi) : "l"(v));
}
__device__ __forceinline__ float sigm(float x) { return 1.0f / (1.0f + expf(-x)); }

struct Common {
    float pe[2][16];     // le_b + sigmoid(p_w[e]) @ le_w[0:4]   (32)
    float ledw[4][16];   // le_w rows 4..7                        (64)
    float sdw[4];        // d_w                                   (4)
    float sdb[4];        // d_b                                   (4)
    float Wuv[40][18];   // rows 0..19: lc_w[o][0:16]; 20..39: lc_w[o][16:32]; pad 2 (720)
    float lcb[20];       // lc_b                                  (20)
    float rsel[2][20];   // relu(rc_w @ relu(rel_w[e]) + rc_b)    (40)
    float hw[20][20];    // h_w row-major                         (400)
    float2 hbm[20];      // {h_b[o], bm_w[o]}                     (40)
    int   msk[56];       // comp_mask flattened
    int   ppair[16];     // phase_pairs flattened
    float bmb;
    float pad0;
    int   pad1[2];
};

struct WScr {
    float demE[12][4];   // 48
    float lane[12][16];  // 192
    float pairs[8][16];  // 128
    float uvb[2][8][20]; // 320   u then v
    float sv[56];        // 56
    float pad[4];        // -> 748 floats = 2992 B (16B multiple)
};

__global__ void __launch_bounds__(256) frap_kernel(
    const float* __restrict__ states,
    const int*   __restrict__ comp_mask,
    const int*   __restrict__ phase_pairs,
    const float* __restrict__ p_w,
    const float* __restrict__ d_w,  const float* __restrict__ d_b,
    const float* __restrict__ le_w, const float* __restrict__ le_b,
    const float* __restrict__ lc_w, const float* __restrict__ lc_b,
    const float* __restrict__ rel_w,
    const float* __restrict__ rc_w, const float* __restrict__ rc_b,
    const float* __restrict__ h_w,  const float* __restrict__ h_b,
    const float* __restrict__ bm_w, const float* __restrict__ bm_b,
    float* __restrict__ out, int Btot, int iters)
{
    __shared__ __align__(16) Common sc;
    __shared__ __align__(16) WScr   ws[8];

    const int tid = threadIdx.x;

    // ---------------- block-wide weight preprocessing ----------------
    for (int idx = tid; idx < 640; idx += 256) {
        int row = idx >> 4, k = idx & 15;
        sc.Wuv[row][k] = lc_w[(row % 20) * 32 + (row / 20) * 16 + k];
    }
    for (int idx = tid; idx < 400; idx += 256)
        sc.hw[idx / 20][idx % 20] = h_w[idx];
    if (tid < 32) {
        int e = tid >> 4, k = tid & 15;
        float acc = le_b[k];
        #pragma unroll
        for (int c = 0; c < 4; c++) acc += sigm(p_w[e * 4 + c]) * le_w[c * 16 + k];
        sc.pe[e][k] = acc;
    }
    if (tid < 64) {
        int c = tid >> 4, k = tid & 15;
        sc.ledw[c][k] = le_w[(4 + c) * 16 + k];
    }
    if (tid < 4) { sc.sdw[tid] = d_w[tid]; sc.sdb[tid] = d_b[tid]; }
    if (tid < 20) sc.lcb[tid] = lc_b[tid];
    if (tid < 40) {
        int e = tid / 20, o = tid % 20;
        float acc = rc_b[o];
        #pragma unroll
        for (int d = 0; d < 4; d++) acc += fmaxf(rel_w[e * 4 + d], 0.f) * rc_w[o * 4 + d];
        sc.rsel[e][o] = fmaxf(acc, 0.f);
    }
    if (tid < 20) sc.hbm[tid] = make_float2(h_b[tid], bm_w[tid]);
    if (tid < 56) sc.msk[tid] = comp_mask[tid];
    if (tid < 16) sc.ppair[tid] = phase_pairs[tid];
    if (tid == 0) sc.bmb = bm_b[0];
    __syncthreads();

    const int warp = tid >> 5;
    const int lane = tid & 31;
    WScr& W = ws[warp];

    for (int it = 0; it < iters; ++it) {
        int b = (blockIdx.x * 8 + warp) + it * (gridDim.x * 8);
        if (b >= Btot) break;
        const float* st = states + b * 13;

        const int act = (int)st[0];
        const int pr0 = sc.ppair[act * 2];
        const int pr1 = sc.ppair[act * 2 + 1];

        // demand embedding: lanes 0..11, one movement each
        if (lane < 12) {
            float dm = st[1 + lane];
            #pragma unroll
            for (int c = 0; c < 4; c++)
                W.demE[lane][c] = sigm(fmaf(dm, sc.sdw[c], sc.sdb[c]));
        }
        __syncwarp();

        // lane embedding: 192 values, 6 per lane
        #pragma unroll
        for (int r = 0; r < 6; r++) {
            int idx = lane + 32 * r;
            int m = idx >> 4, k = idx & 15;
            int e = (m == pr0 || m == pr1) ? 1 : 0;
            float acc = sc.pe[e][k];
            #pragma unroll
            for (int c = 0; c < 4; c++) acc = fmaf(W.demE[m][c], sc.ledw[c][k], acc);
            W.lane[m][k] = fmaxf(acc, 0.f);
        }
        __syncwarp();

        // per-phase pairs: 128 values, 4 per lane
        #pragma unroll
        for (int r = 0; r < 4; r++) {
            int idx = lane + 32 * r;
            int p = idx >> 4, k = idx & 15;
            W.pairs[p][k] = W.lane[sc.ppair[2 * p]][k] + W.lane[sc.ppair[2 * p + 1]][k];
        }
        __syncwarp();

        // u/v: 320 outputs, 10 per lane, packed f32x2 dot-16
        #pragma unroll
        for (int r = 0; r < 10; r++) {
            int oi = lane + 32 * r;
            int p = oi / 40, row = oi % 40;
            const ull* pr2 = (const ull*)&W.pairs[p][0];
            const ull* wr  = (const ull*)&sc.Wuv[row][0];
            ull a = 0;
            #pragma unroll
            for (int k2 = 0; k2 < 8; k2++) a = ffma2(pr2[k2], wr[k2], a);
            float lo, hi; upk2(a, lo, hi);
            float val = lo + hi + ((row < 20) ? sc.lcb[row] : 0.f);
            W.uvb[(row < 20) ? 0 : 1][p][row % 20] = val;
        }
        __syncwarp();

        // main loop: lane handles pairs t0=lane and t1=lane+32 (if <56)
        const int t0 = lane;
        const int i0 = t0 / 7, q0 = t0 % 7;
        const int j0 = q0 + (q0 >= i0 ? 1 : 0);
        const bool valid1 = (lane < 24);
        const int t1 = valid1 ? (lane + 32) : lane;
        const int i1 = t1 / 7, q1 = t1 % 7;
        const int j1 = q1 + (q1 >= i1 ? 1 : 0);
        const float* rs0 = sc.rsel[sc.msk[t0]];
        const float* rs1 = sc.rsel[sc.msk[t1]];

        ull cA[10], cB[10];
        #pragma unroll
        for (int c2 = 0; c2 < 10; c2++) {
            float2 u0 = *(const float2*)&W.uvb[0][i0][2 * c2];
            float2 v0 = *(const float2*)&W.uvb[1][j0][2 * c2];
            float2 r0 = *(const float2*)&rs0[2 * c2];
            cA[c2] = pk2(fmaxf(u0.x + v0.x, 0.f) * r0.x,
                         fmaxf(u0.y + v0.y, 0.f) * r0.y);
            float2 u1 = *(const float2*)&W.uvb[0][i1][2 * c2];
            float2 v1 = *(const float2*)&W.uvb[1][j1][2 * c2];
            float2 r1 = *(const float2*)&rs1[2 * c2];
            cB[c2] = pk2(fmaxf(u1.x + v1.x, 0.f) * r1.x,
                         fmaxf(u1.y + v1.y, 0.f) * r1.y);
        }

        float s0 = 0.f, s1 = 0.f;
        #pragma unroll 4
        for (int o = 0; o < 20; o++) {
            const ull* hr = (const ull*)&sc.hw[o][0];
            ull a0 = 0, a1 = 0;
            #pragma unroll
            for (int c2 = 0; c2 < 10; c2++) {
                ull h2 = hr[c2];
                a0 = ffma2(cA[c2], h2, a0);
                a1 = ffma2(cB[c2], h2, a1);
            }
            float2 hb = sc.hbm[o];
            float l, h;
            upk2(a0, l, h);
            float y0 = fmaxf(l + h + hb.x, 0.f);
            s0 = fmaf(y0, hb.y, s0);
            upk2(a1, l, h);
            float y1 = fmaxf(l + h + hb.x, 0.f);
            s1 = fmaf(y1, hb.y, s1);
        }
        W.sv[t0] = s0 + sc.bmb;
        if (valid1) W.sv[t1] = s1 + sc.bmb;
        __syncwarp();

        // reduce over q dimension (7 entries per phase)
        if (lane < 8) {
            float q = 0.f;
            #pragma unroll
            for (int qq = 0; qq < 7; qq++) q += W.sv[lane * 7 + qq];
            out[b * 8 + lane] = q;
        }
        __syncwarp();
    }
}

extern "C" void kernel_launch(void* const* d_in, const int* in_sizes, int n_in,
                              void* d_out, int out_size)
{
    const float* states      = (const float*)d_in[0];
    const int*   comp_mask   = (const int*)  d_in[1];
    const int*   phase_pairs = (const int*)  d_in[2];
    const float* p_w  = (const float*)d_in[3];
    const float* d_w  = (const float*)d_in[4];
    const float* d_b  = (const float*)d_in[5];
    const float* le_w = (const float*)d_in[6];
    const float* le_b = (const float*)d_in[7];
    const float* lc_w = (const float*)d_in[8];
    const float* lc_b = (const float*)d_in[9];
    const float* rel_w = (const float*)d_in[10];
    const float* rc_w  = (const float*)d_in[11];
    const float* rc_b  = (const float*)d_in[12];
    const float* h_w   = (const float*)d_in[13];
    const float* h_b   = (const float*)d_in[14];
    const float* bm_w  = (const float*)d_in[15];
    const float* bm_b  = (const float*)d_in[16];

    int Btot = in_sizes[0] / 13;          // 32768
    const int iters = 4;                  // batch elements per warp
    int warps_needed = (Btot + iters - 1) / iters;
    int blocks = (warps_needed + 7) / 8;  // 8 warps per block

    frap_kernel<<<blocks, 256>>>(states, comp_mask, phase_pairs, p_w,
                                 d_w, d_b, le_w, le_b, lc_w, lc_b,
                                 rel_w, rc_w, rc_b, h_w, h_b, bm_w, bm_b,
                                 (float*)d_out, Btot, iters);
}

// round 2
// speedup vs baseline: 1.0966x; 1.0966x over previous
#include <cuda_runtime.h>
#include <math.h>

// FRAP q-value kernel, GB300 sm_103a. One warp per batch element.
// Factorization: u[p]=lcA@pairs[p]+lc_b ; v[p]=lcB@pairs[p]
//   comb[i,j] = relu(u[i]+v[j]) * rsel[comp_mask[i,j]]
//   y = relu(h_w@comb + h_b) ; s = bm_w.y + bm_b ; q[i] = sum_j s
// Hot loop uses ld.shared.v2.u64 (128-bit broadcast) of h_w rows feeding
// packed fma.rn.f32x2; comb inputs loaded as float4 (bank-disjoint rows).

typedef unsigned long long ull;

__device__ __forceinline__ ull ffma2(ull a, ull b, ull c) {
    ull d;
    asm("fma.rn.f32x2 %0, %1, %2, %3;" : "=l"(d) : "l"(a), "l"(b), "l"(c));
    return d;
}
__device__ __forceinline__ ull pk2(float lo, float hi) {
    ull r;
    asm("mov.b64 %0, {%1, %2};" : "=l"(r) : "f"(lo), "f"(hi));
    return r;
}
__device__ __forceinline__ void upk2(ull v, float& lo, float& hi) {
    asm("mov.b64 {%0, %1}, %2;" : "=f"(lo), "=f"(hi) : "l"(v));
}
__device__ __forceinline__ float sigm(float x) { return 1.0f / (1.0f + expf(-x)); }

struct __align__(16) Common {
    float pe[2][16];     // le_b + sigmoid(p_w[e]) @ le_w[0:4]
    float ledw[4][16];   // le_w rows 4..7
    float sdw[4];
    float sdb[4];
    float Wuv[40][18];   // rows 0..19: lc_w[o][0:16]; 20..39: lc_w[o][16:32]
    float lcb[20];
    float rsel[2][20];   // relu(rc_w @ relu(rel_w[e]) + rc_b)   (16B aligned rows: off ok)
    float hw[20][20];    // h_w row-major, 80B rows (16B aligned)
    float2 hbm[20];      // {h_b[o], bm_w[o]}
    int   msk[56];
    int   ppair[16];
    float bmb;
    float padf[3];
};

struct __align__(16) WScr {
    float demE[12][4];   // 48
    float lane[12][16];  // 192
    float pairs[8][16];  // 128           (offset 368 floats: 16B aligned)
    float uvb[2][8][20]; // 320  u then v (rows 80B, 16B aligned)
    float sv[56];        // 56
    float pad[4];        // total 748 floats = 2992 B
};

__global__ void __launch_bounds__(256) frap_kernel(
    const float* __restrict__ states,
    const int*   __restrict__ comp_mask,
    const int*   __restrict__ phase_pairs,
    const float* __restrict__ p_w,
    const float* __restrict__ d_w,  const float* __restrict__ d_b,
    const float* __restrict__ le_w, const float* __restrict__ le_b,
    const float* __restrict__ lc_w, const float* __restrict__ lc_b,
    const float* __restrict__ rel_w,
    const float* __restrict__ rc_w, const float* __restrict__ rc_b,
    const float* __restrict__ h_w,  const float* __restrict__ h_b,
    const float* __restrict__ bm_w, const float* __restrict__ bm_b,
    float* __restrict__ out, int Btot, int iters)
{
    __shared__ Common sc;
    __shared__ WScr   ws[8];

    const int tid = threadIdx.x;

    // ---------------- block-wide weight preprocessing ----------------
    for (int idx = tid; idx < 640; idx += 256) {
        int row = idx >> 4, k = idx & 15;
        sc.Wuv[row][k] = lc_w[(row % 20) * 32 + (row / 20) * 16 + k];
    }
    for (int idx = tid; idx < 400; idx += 256)
        sc.hw[idx / 20][idx % 20] = h_w[idx];
    if (tid < 32) {
        int e = tid >> 4, k = tid & 15;
        float acc = le_b[k];
        #pragma unroll
        for (int c = 0; c < 4; c++) acc += sigm(p_w[e * 4 + c]) * le_w[c * 16 + k];
        sc.pe[e][k] = acc;
    }
    if (tid < 64) {
        int c = tid >> 4, k = tid & 15;
        sc.ledw[c][k] = le_w[(4 + c) * 16 + k];
    }
    if (tid < 4) { sc.sdw[tid] = d_w[tid]; sc.sdb[tid] = d_b[tid]; }
    if (tid < 20) sc.lcb[tid] = lc_b[tid];
    if (tid < 40) {
        int e = tid / 20, o = tid % 20;
        float acc = rc_b[o];
        #pragma unroll
        for (int d = 0; d < 4; d++) acc += fmaxf(rel_w[e * 4 + d], 0.f) * rc_w[o * 4 + d];
        sc.rsel[e][o] = fmaxf(acc, 0.f);
    }
    if (tid < 20) sc.hbm[tid] = make_float2(h_b[tid], bm_w[tid]);
    if (tid < 56) sc.msk[tid] = comp_mask[tid];
    if (tid < 16) sc.ppair[tid] = phase_pairs[tid];
    if (tid == 0) sc.bmb = bm_b[0];
    __syncthreads();

    const int warp = tid >> 5;
    const int lane = tid & 31;
    WScr& W = ws[warp];

    // t-slot geometry (loop-invariant)
    const int t0 = lane;
    const int i0 = t0 / 7, q0 = t0 % 7;
    const int j0 = q0 + (q0 >= i0 ? 1 : 0);
    const bool valid1 = (lane < 24);
    const int t1 = valid1 ? (lane + 32) : lane;
    const int i1 = t1 / 7, q1 = t1 % 7;
    const int j1 = q1 + (q1 >= i1 ? 1 : 0);
    const float* rs0 = sc.rsel[sc.msk[t0]];
    const float* rs1 = sc.rsel[sc.msk[t1]];
    const float* u0p = &W.uvb[0][i0][0];
    const float* v0p = &W.uvb[1][j0][0];
    const float* u1p = &W.uvb[0][i1][0];
    const float* v1p = &W.uvb[1][j1][0];

    for (int it = 0; it < iters; ++it) {
        int b = (blockIdx.x * 8 + warp) + it * (gridDim.x * 8);
        if (b >= Btot) break;
        const float* st = states + b * 13;

        const int act = (int)st[0];
        const int pr0 = sc.ppair[act * 2];
        const int pr1 = sc.ppair[act * 2 + 1];

        // demand embedding: lanes 0..11
        if (lane < 12) {
            float dm = st[1 + lane];
            #pragma unroll
            for (int c = 0; c < 4; c++)
                W.demE[lane][c] = sigm(fmaf(dm, sc.sdw[c], sc.sdb[c]));
        }
        __syncwarp();

        // lane embedding: 192 values, 6 per lane
        #pragma unroll
        for (int r = 0; r < 6; r++) {
            int idx = lane + 32 * r;
            int m = idx >> 4, k = idx & 15;
            int e = (m == pr0 || m == pr1) ? 1 : 0;
            float acc = sc.pe[e][k];
            #pragma unroll
            for (int c = 0; c < 4; c++) acc = fmaf(W.demE[m][c], sc.ledw[c][k], acc);
            W.lane[m][k] = fmaxf(acc, 0.f);
        }
        __syncwarp();

        // per-phase pairs: 128 values, 4 per lane
        #pragma unroll
        for (int r = 0; r < 4; r++) {
            int idx = lane + 32 * r;
            int p = idx >> 4, k = idx & 15;
            W.pairs[p][k] = W.lane[sc.ppair[2 * p]][k] + W.lane[sc.ppair[2 * p + 1]][k];
        }
        __syncwarp();

        // u/v: 320 outputs, 10 per lane, packed f32x2 dot-16
        #pragma unroll
        for (int r = 0; r < 10; r++) {
            int oi = lane + 32 * r;
            int p = oi / 40, row = oi % 40;
            const ull* pr2 = (const ull*)&W.pairs[p][0];
            const ull* wr  = (const ull*)&sc.Wuv[row][0];
            ull a = 0;
            #pragma unroll
            for (int k2 = 0; k2 < 8; k2++) a = ffma2(pr2[k2], wr[k2], a);
            float lo, hi; upk2(a, lo, hi);
            float val = lo + hi + ((row < 20) ? sc.lcb[row] : 0.f);
            W.uvb[(row < 20) ? 0 : 1][p][row % 20] = val;
        }
        __syncwarp();

        // comb construction: float4 loads (phase rows hit disjoint bank quartets)
        ull cA[10], cB[10];
        #pragma unroll
        for (int c4 = 0; c4 < 5; c4++) {
            float4 u0 = *(const float4*)(u0p + 4 * c4);
            float4 v0 = *(const float4*)(v0p + 4 * c4);
            float4 r0 = *(const float4*)(rs0 + 4 * c4);
            cA[2 * c4]     = pk2(fmaxf(u0.x + v0.x, 0.f) * r0.x,
                                 fmaxf(u0.y + v0.y, 0.f) * r0.y);
            cA[2 * c4 + 1] = pk2(fmaxf(u0.z + v0.z, 0.f) * r0.z,
                                 fmaxf(u0.w + v0.w, 0.f) * r0.w);
            float4 u1 = *(const float4*)(u1p + 4 * c4);
            float4 v1 = *(const float4*)(v1p + 4 * c4);
            float4 r1 = *(const float4*)(rs1 + 4 * c4);
            cB[2 * c4]     = pk2(fmaxf(u1.x + v1.x, 0.f) * r1.x,
                                 fmaxf(u1.y + v1.y, 0.f) * r1.y);
            cB[2 * c4 + 1] = pk2(fmaxf(u1.z + v1.z, 0.f) * r1.z,
                                 fmaxf(u1.w + v1.w, 0.f) * r1.w);
        }

        // hidden GEMM: 128-bit broadcast loads of h_w rows -> register pairs
        float s0 = 0.f, s1 = 0.f;
        #pragma unroll 4
        for (int o = 0; o < 20; o++) {
            const ulonglong2* hr = (const ulonglong2*)&sc.hw[o][0];
            ull a0 = 0, a1 = 0;
            #pragma unroll
            for (int c4 = 0; c4 < 5; c4++) {
                ulonglong2 h2 = hr[c4];
                a0 = ffma2(cA[2 * c4], h2.x, a0);
                a1 = ffma2(cB[2 * c4], h2.x, a1);
                a0 = ffma2(cA[2 * c4 + 1], h2.y, a0);
                a1 = ffma2(cB[2 * c4 + 1], h2.y, a1);
            }
            float2 hb = sc.hbm[o];
            float l, h;
            upk2(a0, l, h);
            s0 = fmaf(fmaxf(l + h + hb.x, 0.f), hb.y, s0);
            upk2(a1, l, h);
            s1 = fmaf(fmaxf(l + h + hb.x, 0.f), hb.y, s1);
        }
        W.sv[t0] = s0 + sc.bmb;
        if (valid1) W.sv[t1] = s1 + sc.bmb;
        __syncwarp();

        // reduce over q dimension (7 entries per phase)
        if (lane < 8) {
            float q = 0.f;
            #pragma unroll
            for (int qq = 0; qq < 7; qq++) q += W.sv[lane * 7 + qq];
            out[b * 8 + lane] = q;
        }
        __syncwarp();
    }
}

extern "C" void kernel_launch(void* const* d_in, const int* in_sizes, int n_in,
                              void* d_out, int out_size)
{
    const float* states      = (const float*)d_in[0];
    const int*   comp_mask   = (const int*)  d_in[1];
    const int*   phase_pairs = (const int*)  d_in[2];
    const float* p_w  = (const float*)d_in[3];
    const float* d_w  = (const float*)d_in[4];
    const float* d_b  = (const float*)d_in[5];
    const float* le_w = (const float*)d_in[6];
    const float* le_b = (const float*)d_in[7];
    const float* lc_w = (const float*)d_in[8];
    const float* lc_b = (const float*)d_in[9];
    const float* rel_w = (const float*)d_in[10];
    const float* rc_w  = (const float*)d_in[11];
    const float* rc_b  = (const float*)d_in[12];
    const float* h_w   = (const float*)d_in[13];
    const float* h_b   = (const float*)d_in[14];
    const float* bm_w  = (const float*)d_in[15];
    const float* bm_b  = (const float*)d_in[16];

    int Btot = in_sizes[0] / 13;          // 32768
    // Persistent single-wave grid: 152 SMs * 2 CTAs/SM (regs=128 -> 2 resident)
    int blocks = 304;
    int warps  = blocks * 8;
    int iters  = (Btot + warps - 1) / warps;   // 14 for B=32768

    frap_kernel<<<blocks, 256>>>(states, comp_mask, phase_pairs, p_w,
                                 d_w, d_b, le_w, le_b, lc_w, lc_b,
                                 rel_w, rc_w, rc_b, h_w, h_b, bm_w, bm_b,
                                 (float*)d_out, Btot, iters);
}

// round 6
// speedup vs baseline: 1.2049x; 1.0988x over previous
#include <cuda_runtime.h>
#include <math.h>

// FRAP q-value kernel, GB300 sm_103a. One warp per batch element.
// Factorization: u[p]=lcA@pairs[p]+lc_b ; v[p]=lcB@pairs[p]
//   comb[i,j] = relu(u[i]+v[j]) * rsel[comp_mask[i,j]]
//   y = relu(h_w@comb + h_b) ; s = bm_w.y + bm_b ; q[i] = sum_j s
// R5 (re-bench of R3): force 3 CTAs/SM (occ 37.5%) via launch_bounds;
// leaner unrolls to fit 84 regs; persistent 1-wave grid of 456 blocks.

typedef unsigned long long ull;

__device__ __forceinline__ ull ffma2(ull a, ull b, ull c) {
    ull d;
    asm("fma.rn.f32x2 %0, %1, %2, %3;" : "=l"(d) : "l"(a), "l"(b), "l"(c));
    return d;
}
__device__ __forceinline__ ull pk2(float lo, float hi) {
    ull r;
    asm("mov.b64 %0, {%1, %2};" : "=l"(r) : "f"(lo), "f"(hi));
    return r;
}
__device__ __forceinline__ void upk2(ull v, float& lo, float& hi) {
    asm("mov.b64 {%0, %1}, %2;" : "=f"(lo), "=f"(hi) : "l"(v));
}
__device__ __forceinline__ float sigm(float x) { return 1.0f / (1.0f + expf(-x)); }

struct __align__(16) Common {
    float pe[2][16];     // le_b + sigmoid(p_w[e]) @ le_w[0:4]
    float ledw[4][16];   // le_w rows 4..7
    float sdw[4];
    float sdb[4];
    float Wuv[40][18];   // rows 0..19: lc_w[o][0:16]; 20..39: lc_w[o][16:32]
    float lcb[20];
    float rsel[2][20];   // relu(rc_w @ relu(rel_w[e]) + rc_b)
    float hw[20][20];    // h_w row-major, 80B rows (16B aligned)
    float2 hbm[20];      // {h_b[o], bm_w[o]}
    int   msk[56];
    int   ppair[16];
    float bmb;
    float padf[3];
};

struct __align__(16) WScr {
    float demE[12][4];   // 48
    float lane[12][16];  // 192
    float pairs[8][16];  // 128
    float uvb[2][8][20]; // 320  u then v (rows 80B, 16B aligned)
    float sv[56];        // 56
    float pad[4];        // total 748 floats = 2992 B
};

__global__ void __launch_bounds__(256, 3) frap_kernel(
    const float* __restrict__ states,
    const int*   __restrict__ comp_mask,
    const int*   __restrict__ phase_pairs,
    const float* __restrict__ p_w,
    const float* __restrict__ d_w,  const float* __restrict__ d_b,
    const float* __restrict__ le_w, const float* __restrict__ le_b,
    const float* __restrict__ lc_w, const float* __restrict__ lc_b,
    const float* __restrict__ rel_w,
    const float* __restrict__ rc_w, const float* __restrict__ rc_b,
    const float* __restrict__ h_w,  const float* __restrict__ h_b,
    const float* __restrict__ bm_w, const float* __restrict__ bm_b,
    float* __restrict__ out, int Btot, int iters)
{
    __shared__ Common sc;
    __shared__ WScr   ws[8];

    const int tid = threadIdx.x;

    // ---------------- block-wide weight preprocessing ----------------
    for (int idx = tid; idx < 640; idx += 256) {
        int row = idx >> 4, k = idx & 15;
        sc.Wuv[row][k] = lc_w[(row % 20) * 32 + (row / 20) * 16 + k];
    }
    for (int idx = tid; idx < 400; idx += 256)
        sc.hw[idx / 20][idx % 20] = h_w[idx];
    if (tid < 32) {
        int e = tid >> 4, k = tid & 15;
        float acc = le_b[k];
        #pragma unroll
        for (int c = 0; c < 4; c++) acc += sigm(p_w[e * 4 + c]) * le_w[c * 16 + k];
        sc.pe[e][k] = acc;
    }
    if (tid < 64) {
        int c = tid >> 4, k = tid & 15;
        sc.ledw[c][k] = le_w[(4 + c) * 16 + k];
    }
    if (tid < 4) { sc.sdw[tid] = d_w[tid]; sc.sdb[tid] = d_b[tid]; }
    if (tid < 20) sc.lcb[tid] = lc_b[tid];
    if (tid < 40) {
        int e = tid / 20, o = tid % 20;
        float acc = rc_b[o];
        #pragma unroll
        for (int d = 0; d < 4; d++) acc += fmaxf(rel_w[e * 4 + d], 0.f) * rc_w[o * 4 + d];
        sc.rsel[e][o] = fmaxf(acc, 0.f);
    }
    if (tid < 20) sc.hbm[tid] = make_float2(h_b[tid], bm_w[tid]);
    if (tid < 56) sc.msk[tid] = comp_mask[tid];
    if (tid < 16) sc.ppair[tid] = phase_pairs[tid];
    if (tid == 0) sc.bmb = bm_b[0];
    __syncthreads();

    const int warp = tid >> 5;
    const int lane = tid & 31;
    WScr& W = ws[warp];

    // t-slot geometry (loop-invariant)
    const int t0 = lane;
    const int i0 = t0 / 7, q0 = t0 % 7;
    const int j0 = q0 + (q0 >= i0 ? 1 : 0);
    const bool valid1 = (lane < 24);
    const int t1 = valid1 ? (lane + 32) : lane;
    const int i1 = t1 / 7, q1 = t1 % 7;
    const int j1 = q1 + (q1 >= i1 ? 1 : 0);
    const float* rs0 = sc.rsel[sc.msk[t0]];
    const float* rs1 = sc.rsel[sc.msk[t1]];
    const float* u0p = &W.uvb[0][i0][0];
    const float* v0p = &W.uvb[1][j0][0];
    const float* u1p = &W.uvb[0][i1][0];
    const float* v1p = &W.uvb[1][j1][0];

    for (int it = 0; it < iters; ++it) {
        int b = (blockIdx.x * 8 + warp) + it * (gridDim.x * 8);
        if (b >= Btot) break;
        const float* st = states + b * 13;

        const int act = (int)st[0];
        const int pr0 = sc.ppair[act * 2];
        const int pr1 = sc.ppair[act * 2 + 1];

        // demand embedding: lanes 0..11, one float4 store each
        if (lane < 12) {
            float dm = st[1 + lane];
            float4 de;
            de.x = sigm(fmaf(dm, sc.sdw[0], sc.sdb[0]));
            de.y = sigm(fmaf(dm, sc.sdw[1], sc.sdb[1]));
            de.z = sigm(fmaf(dm, sc.sdw[2], sc.sdb[2]));
            de.w = sigm(fmaf(dm, sc.sdw[3], sc.sdb[3]));
            *(float4*)&W.demE[lane][0] = de;
        }
        __syncwarp();

        // lane embedding: 192 values, 6 per lane
        #pragma unroll
        for (int r = 0; r < 6; r++) {
            int idx = lane + 32 * r;
            int m = idx >> 4, k = idx & 15;
            int e = (m == pr0 || m == pr1) ? 1 : 0;
            float acc = sc.pe[e][k];
            #pragma unroll
            for (int c = 0; c < 4; c++) acc = fmaf(W.demE[m][c], sc.ledw[c][k], acc);
            W.lane[m][k] = fmaxf(acc, 0.f);
        }
        __syncwarp();

        // per-phase pairs: 128 values, 4 per lane
        #pragma unroll
        for (int r = 0; r < 4; r++) {
            int idx = lane + 32 * r;
            int p = idx >> 4, k = idx & 15;
            W.pairs[p][k] = W.lane[sc.ppair[2 * p]][k] + W.lane[sc.ppair[2 * p + 1]][k];
        }
        __syncwarp();

        // u/v: 320 outputs, 10 per lane (unroll 5 to limit live registers)
        #pragma unroll 5
        for (int r = 0; r < 10; r++) {
            int oi = lane + 32 * r;
            int p = oi / 40, row = oi % 40;
            const ull* pr2 = (const ull*)&W.pairs[p][0];
            const ull* wr  = (const ull*)&sc.Wuv[row][0];
            ull a = 0;
            #pragma unroll
            for (int k2 = 0; k2 < 8; k2++) a = ffma2(pr2[k2], wr[k2], a);
            float lo, hi; upk2(a, lo, hi);
            float val = lo + hi + ((row < 20) ? sc.lcb[row] : 0.f);
            W.uvb[(row < 20) ? 0 : 1][p][row % 20] = val;
        }
        __syncwarp();

        // comb construction: float4 loads (phase rows hit disjoint bank quartets)
        ull cA[10], cB[10];
        #pragma unroll
        for (int c4 = 0; c4 < 5; c4++) {
            float4 u0 = *(const float4*)(u0p + 4 * c4);
            float4 v0 = *(const float4*)(v0p + 4 * c4);
            float4 r0 = *(const float4*)(rs0 + 4 * c4);
            cA[2 * c4]     = pk2(fmaxf(u0.x + v0.x, 0.f) * r0.x,
                                 fmaxf(u0.y + v0.y, 0.f) * r0.y);
            cA[2 * c4 + 1] = pk2(fmaxf(u0.z + v0.z, 0.f) * r0.z,
                                 fmaxf(u0.w + v0.w, 0.f) * r0.w);
            float4 u1 = *(const float4*)(u1p + 4 * c4);
            float4 v1 = *(const float4*)(v1p + 4 * c4);
            float4 r1 = *(const float4*)(rs1 + 4 * c4);
            cB[2 * c4]     = pk2(fmaxf(u1.x + v1.x, 0.f) * r1.x,
                                 fmaxf(u1.y + v1.y, 0.f) * r1.y);
            cB[2 * c4 + 1] = pk2(fmaxf(u1.z + v1.z, 0.f) * r1.z,
                                 fmaxf(u1.w + v1.w, 0.f) * r1.w);
        }

        // hidden GEMM: 128-bit broadcast loads of h_w rows (unroll 2)
        float s0 = 0.f, s1 = 0.f;
        #pragma unroll 2
        for (int o = 0; o < 20; o++) {
            const ulonglong2* hr = (const ulonglong2*)&sc.hw[o][0];
            ull a0 = 0, a1 = 0;
            #pragma unroll
            for (int c4 = 0; c4 < 5; c4++) {
                ulonglong2 h2 = hr[c4];
                a0 = ffma2(cA[2 * c4], h2.x, a0);
                a1 = ffma2(cB[2 * c4], h2.x, a1);
                a0 = ffma2(cA[2 * c4 + 1], h2.y, a0);
                a1 = ffma2(cB[2 * c4 + 1], h2.y, a1);
            }
            float2 hb = sc.hbm[o];
            float l, h;
            upk2(a0, l, h);
            s0 = fmaf(fmaxf(l + h + hb.x, 0.f), hb.y, s0);
            upk2(a1, l, h);
            s1 = fmaf(fmaxf(l + h + hb.x, 0.f), hb.y, s1);
        }
        W.sv[t0] = s0 + sc.bmb;
        if (valid1) W.sv[t1] = s1 + sc.bmb;
        __syncwarp();

        // reduce over q dimension (7 entries per phase)
        if (lane < 8) {
            float q = 0.f;
            #pragma unroll
            for (int qq = 0; qq < 7; qq++) q += W.sv[lane * 7 + qq];
            out[b * 8 + lane] = q;
        }
        __syncwarp();
    }
}

extern "C" void kernel_launch(void* const* d_in, const int* in_sizes, int n_in,
                              void* d_out, int out_size)
{
    const float* states      = (const float*)d_in[0];
    const int*   comp_mask   = (const int*)  d_in[1];
    const int*   phase_pairs = (const int*)  d_in[2];
    const float* p_w  = (const float*)d_in[3];
    const float* d_w  = (const float*)d_in[4];
    const float* d_b  = (const float*)d_in[5];
    const float* le_w = (const float*)d_in[6];
    const float* le_b = (const float*)d_in[7];
    const float* lc_w = (const float*)d_in[8];
    const float* lc_b = (const float*)d_in[9];
    const float* rel_w = (const float*)d_in[10];
    const float* rc_w  = (const float*)d_in[11];
    const float* rc_b  = (const float*)d_in[12];
    const float* h_w   = (const float*)d_in[13];
    const float* h_b   = (const float*)d_in[14];
    const float* bm_w  = (const float*)d_in[15];
    const float* bm_b  = (const float*)d_in[16];

    int Btot = in_sizes[0] / 13;          // 32768
    // Persistent single-wave grid: 152 SMs * 3 CTAs/SM
    int blocks = 456;
    int warps  = blocks * 8;              // 3648 warps
    int iters  = (Btot + warps - 1) / warps;   // 9 for B=32768

    frap_kernel<<<blocks, 256>>>(states, comp_mask, phase_pairs, p_w,
                                 d_w, d_b, le_w, le_b, lc_w, lc_b,
                                 rel_w, rc_w, rc_b, h_w, h_b, bm_w, bm_b,
                                 (float*)d_out, Btot, iters);
}